// round 8
// baseline (speedup 1.0000x reference)
#include <cuda_runtime.h>
#include <cuda_bf16.h>

// Problem constants
#define BB 8
#define C1 128
#define C2 256
#define NN 1024
#define HEADS 8
#define DD 32
#define KC 3
#define SCALE 0.17677669529663687f   // 32^-0.5
#define LOG2E 1.4426950408889634f
#define QSC (SCALE * LOG2E)

// Scratch (device globals; no allocation allowed)
__device__ float g_xf[BB * C2 * NN];        // proj_in out / identity [b][c][n]
__device__ float g_prob[BB * KC * NN];      // cluster probs [b][k][n]
__device__ float g_qkv[BB * 3 * C2 * NN];   // qkv [b][o][n]
__device__ float g_att[BB * C2 * NN];       // attention out [b][c][n]

// ---------------------------------------------------------------------------
__device__ __forceinline__ float ex2(float x) {
    float r; asm("ex2.approx.f32 %0, %1;" : "=f"(r) : "f"(x)); return r;
}
__device__ __forceinline__ unsigned pack_bf2(float lo, float hi) {
    unsigned r;
    asm("cvt.rn.bf16x2.f32 %0, %1, %2;" : "=r"(r) : "f"(hi), "f"(lo));
    return r;
}
__device__ __forceinline__ unsigned saddr(const void* p) {
    return (unsigned)__cvta_generic_to_shared(p);
}
__device__ __forceinline__ void ldsm4(unsigned& r0, unsigned& r1, unsigned& r2, unsigned& r3, unsigned a) {
    asm volatile("ldmatrix.sync.aligned.m8n8.x4.shared.b16 {%0,%1,%2,%3}, [%4];"
                 : "=r"(r0), "=r"(r1), "=r"(r2), "=r"(r3) : "r"(a));
}
__device__ __forceinline__ void ldsm2(unsigned& r0, unsigned& r1, unsigned a) {
    asm volatile("ldmatrix.sync.aligned.m8n8.x2.shared.b16 {%0,%1}, [%2];"
                 : "=r"(r0), "=r"(r1) : "r"(a));
}
__device__ __forceinline__ void ldsm4t(unsigned& r0, unsigned& r1, unsigned& r2, unsigned& r3, unsigned a) {
    asm volatile("ldmatrix.sync.aligned.m8n8.x4.trans.shared.b16 {%0,%1,%2,%3}, [%4];"
                 : "=r"(r0), "=r"(r1), "=r"(r2), "=r"(r3) : "r"(a));
}
__device__ __forceinline__ void mma16(float* c, const unsigned* a, unsigned b0, unsigned b1) {
    asm volatile(
        "mma.sync.aligned.m16n8k16.row.col.f32.bf16.bf16.f32 "
        "{%0,%1,%2,%3}, {%4,%5,%6,%7}, {%8,%9}, {%0,%1,%2,%3};"
        : "+f"(c[0]), "+f"(c[1]), "+f"(c[2]), "+f"(c[3])
        : "r"(a[0]), "r"(a[1]), "r"(a[2]), "r"(a[3]), "r"(b0), "r"(b1));
}

// ---------------------------------------------------------------------------
// bf16 tensor-core GEMM: C[bz] = A(MxK)@B[bz](KxN) (+Res[bz])
// 128x128 tile, kstep 32, 8 warps (2x4), each warp 64x32 via m16n8k16.
// ---------------------------------------------------------------------------
template <bool ADD_RES>
__global__ __launch_bounds__(256, 2) void gemm_bf16(
    const float* __restrict__ A, const float* __restrict__ Bmat,
    float* __restrict__ C, const float* __restrict__ Res,
    int M, int N, int K)
{
    const int n0 = blockIdx.x * 128;
    const int m0 = blockIdx.y * 128;
    const int bz = blockIdx.z;
    Bmat += (size_t)bz * K * N;
    C    += (size_t)bz * M * N;
    const float* R = ADD_RES ? (Res + (size_t)bz * M * N) : nullptr;

    __shared__ __align__(16) __nv_bfloat16 As[128][40];
    __shared__ __align__(16) __nv_bfloat16 Bs[32][136];

    const int t    = threadIdx.x;
    const int lane = t & 31;
    const int w    = t >> 5;
    const int g    = lane >> 2;
    const int tg   = lane & 3;
    const int wm   = (w >> 2) * 64;
    const int wn   = (w & 3) * 32;

    float acc[4][4][4];
#pragma unroll
    for (int mb = 0; mb < 4; mb++)
#pragma unroll
        for (int nb = 0; nb < 4; nb++)
#pragma unroll
            for (int e = 0; e < 4; e++) acc[mb][nb][e] = 0.f;

    const int lam = t >> 3, lak = (t & 7) * 4;
    const int lbk = t >> 5, lbn = (t & 31) * 4;

    for (int kt = 0; kt < K; kt += 32) {
        __syncthreads();
#pragma unroll
        for (int p = 0; p < 4; p++) {
            float4 v = *(const float4*)&A[(size_t)(m0 + lam + 32 * p) * K + kt + lak];
            *(unsigned*)&As[lam + 32 * p][lak]     = pack_bf2(v.x, v.y);
            *(unsigned*)&As[lam + 32 * p][lak + 2] = pack_bf2(v.z, v.w);
        }
#pragma unroll
        for (int p = 0; p < 4; p++) {
            float4 v = *(const float4*)&Bmat[(size_t)(kt + lbk + 8 * p) * N + n0 + lbn];
            *(unsigned*)&Bs[lbk + 8 * p][lbn]     = pack_bf2(v.x, v.y);
            *(unsigned*)&Bs[lbk + 8 * p][lbn + 2] = pack_bf2(v.z, v.w);
        }
        __syncthreads();
#pragma unroll
        for (int ks = 0; ks < 2; ks++) {
            unsigned a[4][4], bb[2][4];
#pragma unroll
            for (int mb = 0; mb < 4; mb++) {
                int row = wm + 16 * mb + (lane & 7) + ((lane & 8) ? 8 : 0);
                int col = 16 * ks + ((lane >= 16) ? 8 : 0);
                ldsm4(a[mb][0], a[mb][1], a[mb][2], a[mb][3], saddr(&As[row][col]));
            }
#pragma unroll
            for (int np = 0; np < 2; np++) {
                int row = 16 * ks + (lane & 7) + ((lane & 8) ? 8 : 0);
                int col = wn + 16 * np + ((lane >= 16) ? 8 : 0);
                ldsm4t(bb[np][0], bb[np][1], bb[np][2], bb[np][3], saddr(&Bs[row][col]));
            }
#pragma unroll
            for (int mb = 0; mb < 4; mb++)
#pragma unroll
                for (int nb = 0; nb < 4; nb++)
                    mma16(acc[mb][nb], a[mb], bb[nb >> 1][(nb & 1) * 2], bb[nb >> 1][(nb & 1) * 2 + 1]);
        }
    }

#pragma unroll
    for (int mb = 0; mb < 4; mb++) {
        const int mr = m0 + wm + 16 * mb;
#pragma unroll
        for (int nb = 0; nb < 4; nb++) {
            const int nc = n0 + wn + 8 * nb + 2 * tg;
            const size_t i0 = (size_t)(mr + g) * N + nc;
            const size_t i1 = (size_t)(mr + g + 8) * N + nc;
            float2 v0 = make_float2(acc[mb][nb][0], acc[mb][nb][1]);
            float2 v1 = make_float2(acc[mb][nb][2], acc[mb][nb][3]);
            if (ADD_RES) {
                float2 r0 = *(const float2*)&R[i0];
                float2 r1 = *(const float2*)&R[i1];
                v0.x += r0.x; v0.y += r0.y; v1.x += r1.x; v1.y += r1.y;
            }
            *(float2*)&C[i0] = v0;
            *(float2*)&C[i1] = v1;
        }
    }
}

// ---------------------------------------------------------------------------
// Split-bf16 tensor GEMM for proj_in (near-fp32 precision):
// x = hi + lo (two bf16 terms); C = Ah@Bh + Ah@Bl + Al@Bh  (fp32 accum).
// ---------------------------------------------------------------------------
__global__ __launch_bounds__(256, 2) void gemm_split(
    const float* __restrict__ A, const float* __restrict__ Bmat,
    float* __restrict__ C, int M, int N, int K)
{
    const int n0 = blockIdx.x * 128;
    const int m0 = blockIdx.y * 128;
    const int bz = blockIdx.z;
    Bmat += (size_t)bz * K * N;
    C    += (size_t)bz * M * N;

    __shared__ __align__(16) __nv_bfloat16 Ah[128][40];
    __shared__ __align__(16) __nv_bfloat16 Al[128][40];
    __shared__ __align__(16) __nv_bfloat16 Bh[32][136];
    __shared__ __align__(16) __nv_bfloat16 Bl[32][136];

    const int t    = threadIdx.x;
    const int lane = t & 31;
    const int w    = t >> 5;
    const int g    = lane >> 2;
    const int tg   = lane & 3;
    const int wm   = (w >> 2) * 64;
    const int wn   = (w & 3) * 32;

    float acc[4][4][4];
#pragma unroll
    for (int mb = 0; mb < 4; mb++)
#pragma unroll
        for (int nb = 0; nb < 4; nb++)
#pragma unroll
            for (int e = 0; e < 4; e++) acc[mb][nb][e] = 0.f;

    const int lam = t >> 3, lak = (t & 7) * 4;
    const int lbk = t >> 5, lbn = (t & 31) * 4;

    for (int kt = 0; kt < K; kt += 32) {
        __syncthreads();
#pragma unroll
        for (int p = 0; p < 4; p++) {
            float4 v = *(const float4*)&A[(size_t)(m0 + lam + 32 * p) * K + kt + lak];
            unsigned h0 = pack_bf2(v.x, v.y), h1 = pack_bf2(v.z, v.w);
            __nv_bfloat162 b0 = *(__nv_bfloat162*)&h0, b1 = *(__nv_bfloat162*)&h1;
            *(unsigned*)&Ah[lam + 32 * p][lak]     = h0;
            *(unsigned*)&Ah[lam + 32 * p][lak + 2] = h1;
            *(unsigned*)&Al[lam + 32 * p][lak]     = pack_bf2(v.x - __bfloat162float(b0.x), v.y - __bfloat162float(b0.y));
            *(unsigned*)&Al[lam + 32 * p][lak + 2] = pack_bf2(v.z - __bfloat162float(b1.x), v.w - __bfloat162float(b1.y));
        }
#pragma unroll
        for (int p = 0; p < 4; p++) {
            float4 v = *(const float4*)&Bmat[(size_t)(kt + lbk + 8 * p) * N + n0 + lbn];
            unsigned h0 = pack_bf2(v.x, v.y), h1 = pack_bf2(v.z, v.w);
            __nv_bfloat162 b0 = *(__nv_bfloat162*)&h0, b1 = *(__nv_bfloat162*)&h1;
            *(unsigned*)&Bh[lbk + 8 * p][lbn]     = h0;
            *(unsigned*)&Bh[lbk + 8 * p][lbn + 2] = h1;
            *(unsigned*)&Bl[lbk + 8 * p][lbn]     = pack_bf2(v.x - __bfloat162float(b0.x), v.y - __bfloat162float(b0.y));
            *(unsigned*)&Bl[lbk + 8 * p][lbn + 2] = pack_bf2(v.z - __bfloat162float(b1.x), v.w - __bfloat162float(b1.y));
        }
        __syncthreads();
#pragma unroll
        for (int ks = 0; ks < 2; ks++) {
            unsigned ah[4][4], al[4][4], bh[2][4], bl[2][4];
#pragma unroll
            for (int mb = 0; mb < 4; mb++) {
                int row = wm + 16 * mb + (lane & 7) + ((lane & 8) ? 8 : 0);
                int col = 16 * ks + ((lane >= 16) ? 8 : 0);
                ldsm4(ah[mb][0], ah[mb][1], ah[mb][2], ah[mb][3], saddr(&Ah[row][col]));
                ldsm4(al[mb][0], al[mb][1], al[mb][2], al[mb][3], saddr(&Al[row][col]));
            }
#pragma unroll
            for (int np = 0; np < 2; np++) {
                int row = 16 * ks + (lane & 7) + ((lane & 8) ? 8 : 0);
                int col = wn + 16 * np + ((lane >= 16) ? 8 : 0);
                ldsm4t(bh[np][0], bh[np][1], bh[np][2], bh[np][3], saddr(&Bh[row][col]));
                ldsm4t(bl[np][0], bl[np][1], bl[np][2], bl[np][3], saddr(&Bl[row][col]));
            }
#pragma unroll
            for (int mb = 0; mb < 4; mb++)
#pragma unroll
                for (int nb = 0; nb < 4; nb++) {
                    unsigned h0 = bh[nb >> 1][(nb & 1) * 2], h1 = bh[nb >> 1][(nb & 1) * 2 + 1];
                    unsigned l0 = bl[nb >> 1][(nb & 1) * 2], l1 = bl[nb >> 1][(nb & 1) * 2 + 1];
                    mma16(acc[mb][nb], ah[mb], h0, h1);
                    mma16(acc[mb][nb], ah[mb], l0, l1);
                    mma16(acc[mb][nb], al[mb], h0, h1);
                }
        }
    }

#pragma unroll
    for (int mb = 0; mb < 4; mb++) {
        const int mr = m0 + wm + 16 * mb;
#pragma unroll
        for (int nb = 0; nb < 4; nb++) {
            const int nc = n0 + wn + 8 * nb + 2 * tg;
            *(float2*)&C[(size_t)(mr + g) * N + nc]     = make_float2(acc[mb][nb][0], acc[mb][nb][1]);
            *(float2*)&C[(size_t)(mr + g + 8) * N + nc] = make_float2(acc[mb][nb][2], acc[mb][nb][3]);
        }
    }
}

// ---------------------------------------------------------------------------
// Cluster logits + softmax over KC=3
// ---------------------------------------------------------------------------
__global__ __launch_bounds__(256) void cluster_kernel(
    const float* __restrict__ Wc, const float* __restrict__ bc)
{
    const int b = blockIdx.y;
    const int n = blockIdx.x * 256 + threadIdx.x;

    __shared__ float Wcs[KC][C2];
    __shared__ float bcs[KC];
    for (int i = threadIdx.x; i < KC * C2; i += 256) Wcs[i / C2][i % C2] = Wc[i];
    if (threadIdx.x < KC) bcs[threadIdx.x] = bc[threadIdx.x];
    __syncthreads();

    const float* xb = g_xf + (size_t)b * C2 * NN;
    float a0 = bcs[0], a1 = bcs[1], a2 = bcs[2];
#pragma unroll 4
    for (int c = 0; c < C2; c++) {
        float xv = xb[(size_t)c * NN + n];
        a0 += Wcs[0][c] * xv;
        a1 += Wcs[1][c] * xv;
        a2 += Wcs[2][c] * xv;
    }
    float mm = fmaxf(a0, fmaxf(a1, a2));
    float e0 = __expf(a0 - mm), e1 = __expf(a1 - mm), e2 = __expf(a2 - mm);
    float inv = 1.f / (e0 + e1 + e2);
    g_prob[(size_t)(b * KC + 0) * NN + n] = e0 * inv;
    g_prob[(size_t)(b * KC + 1) * NN + n] = e1 * inv;
    g_prob[(size_t)(b * KC + 2) * NN + n] = e2 * inv;
}

// ---------------------------------------------------------------------------
// Clustered attention, bf16 mma, register P.
// Shared raw K tile -> S = Q@K^T ONCE; V prescaled by pk_i into 3 smem tiles
// (one gmem read) with an appended ones-row so PV mma also produces l = sum p.
// 128 threads (4 warps), q-tile 64, k-tile 64 processed in two 32-key chunks.
// ---------------------------------------------------------------------------
#define QP 72  // bf16 pitch
__global__ __launch_bounds__(128, 4) void attn_kernel()
{
    const int q0 = blockIdx.x * 64;
    const int h  = blockIdx.y;
    const int b  = blockIdx.z;
    const int t    = threadIdx.x;
    const int lane = t & 31;
    const int w    = t >> 5;
    const int g    = lane >> 2;
    const int tg   = lane & 3;

    __shared__ __align__(16) char sm[27264];
    __nv_bfloat16* Qds = (__nv_bfloat16*)(sm);          // [32][72] raw q
    __nv_bfloat16* Kds = (__nv_bfloat16*)(sm + 4608);   // [32][72] raw k
    __nv_bfloat16* Vsb = (__nv_bfloat16*)(sm + 9216);   // [3][40][72]: rows0-31 v*pk_i, row32=1, 33-39=0
    float* probKs      = (float*)(sm + 26496);          // [3][64]

    const float* qb = g_qkv + (size_t)(b * 768 + h * DD) * NN;
    const float* kb = qb + (size_t)256 * NN;
    const float* vb = qb + (size_t)512 * NN;
    const float* pb = g_prob + (size_t)b * KC * NN;

    const int ld  = t >> 4;         // 0..7
    const int lt4 = (t & 15) * 4;   // 0..60

    // Q tile: [d][tok] f32 -> bf16
#pragma unroll
    for (int p = 0; p < 4; p++) {
        float4 v = *(const float4*)&qb[(size_t)(ld + 8 * p) * NN + q0 + lt4];
        *(uint2*)&Qds[(ld + 8 * p) * QP + lt4] =
            make_uint2(pack_bf2(v.x, v.y), pack_bf2(v.z, v.w));
    }
    // V static rows: row 32 = 1.0, rows 33..39 = 0 (per cluster)
    for (int idx = t; idx < KC * 8 * QP; idx += 128) {
        int i = idx / (8 * QP), rr = (idx / QP) & 7, c = idx % QP;
        Vsb[(i * 40 + 32 + rr) * QP + c] = __float2bfloat16(rr == 0 ? 1.f : 0.f);
    }
    __syncthreads();

    // Q fragments (loop invariant)
    unsigned aQ[2][4];
#pragma unroll
    for (int ds = 0; ds < 2; ds++) {
        int row = 16 * ds + (lane & 7) + ((lane >= 16) ? 8 : 0);
        int col = 16 * w + ((lane & 8) ? 8 : 0);
        ldsm4t(aQ[ds][0], aQ[ds][1], aQ[ds][2], aQ[ds][3], saddr(&Qds[row * QP + col]));
    }
    float qc[KC][2];
#pragma unroll
    for (int i = 0; i < KC; i++) {
        qc[i][0] = pb[(size_t)i * NN + q0 + 16 * w + g]     * QSC;
        qc[i][1] = pb[(size_t)i * NN + q0 + 16 * w + g + 8] * QSC;
    }

    float acc[KC][4][4];   // O accumulators
    float accl[KC][4];     // l via ones-row mma
#pragma unroll
    for (int i = 0; i < KC; i++) {
#pragma unroll
        for (int e = 0; e < 4; e++) accl[i][e] = 0.f;
#pragma unroll
        for (int jn = 0; jn < 4; jn++)
#pragma unroll
            for (int e = 0; e < 4; e++) acc[i][jn][e] = 0.f;
    }

    for (int k0 = 0; k0 < NN; k0 += 64) {
        __syncthreads();
        float4 pk4[KC];
#pragma unroll
        for (int i = 0; i < KC; i++) pk4[i] = *(const float4*)&pb[(size_t)i * NN + k0 + lt4];
#pragma unroll
        for (int p = 0; p < 4; p++) {
            const int row = ld + 8 * p;
            float4 kv = *(const float4*)&kb[(size_t)row * NN + k0 + lt4];
            float4 vv = *(const float4*)&vb[(size_t)row * NN + k0 + lt4];
            *(uint2*)&Kds[row * QP + lt4] = make_uint2(pack_bf2(kv.x, kv.y), pack_bf2(kv.z, kv.w));
#pragma unroll
            for (int i = 0; i < KC; i++)
                *(uint2*)&Vsb[(i * 40 + row) * QP + lt4] = make_uint2(
                    pack_bf2(vv.x * pk4[i].x, vv.y * pk4[i].y),
                    pack_bf2(vv.z * pk4[i].z, vv.w * pk4[i].w));
        }
        if (t < KC * 64) probKs[t] = pb[(size_t)(t >> 6) * NN + k0 + (t & 63)];
        __syncthreads();

#pragma unroll
        for (int ch = 0; ch < 2; ch++) {
            // S chunk [16 x 32] = Q @ K^T (raw), keys ch*32..+31
            float S[4][4];
#pragma unroll
            for (int j = 0; j < 4; j++)
#pragma unroll
                for (int e = 0; e < 4; e++) S[j][e] = 0.f;
#pragma unroll
            for (int ds = 0; ds < 2; ds++) {
#pragma unroll
                for (int jl = 0; jl < 2; jl++) {
                    const int jp = 2 * ch + jl;
                    unsigned b0a, b1a, b0b, b1b;
                    int row = 16 * ds + (lane & 7) + ((lane & 8) ? 8 : 0);
                    int col = 16 * jp + ((lane >= 16) ? 8 : 0);
                    ldsm4t(b0a, b1a, b0b, b1b, saddr(&Kds[row * QP + col]));
                    mma16(S[2 * jl],     aQ[ds], b0a, b1a);
                    mma16(S[2 * jl + 1], aQ[ds], b0b, b1b);
                }
            }
            // 3 clusters: exp2 + PV (+l) on this chunk
#pragma unroll
            for (int i = 0; i < KC; i++) {
                const float q0c = qc[i][0], q1c = qc[i][1];
                unsigned aP[2][4];
#pragma unroll
                for (int j = 0; j < 4; j++) {
                    const float2 pk = *(const float2*)&probKs[i * 64 + ch * 32 + 8 * j + 2 * tg];
                    float p00 = ex2(q0c * (pk.x * S[j][0]));
                    float p01 = ex2(q0c * (pk.y * S[j][1]));
                    float p10 = ex2(q1c * (pk.x * S[j][2]));
                    float p11 = ex2(q1c * (pk.y * S[j][3]));
                    aP[j >> 1][(j & 1) * 2]     = pack_bf2(p00, p01);
                    aP[j >> 1][(j & 1) * 2 + 1] = pack_bf2(p10, p11);
                }
                const __nv_bfloat16* Vi = Vsb + i * 40 * QP;
#pragma unroll
                for (int kl = 0; kl < 2; kl++) {
                    const int kk = 2 * ch + kl;
#pragma unroll
                    for (int jp = 0; jp < 2; jp++) {
                        unsigned v0, v1, v2, v3;
                        int row = 8 * (2 * jp + ((lane >= 16) ? 1 : 0)) + (lane & 7);
                        int col = 16 * kk + ((lane & 8) ? 8 : 0);
                        ldsm4(v0, v1, v2, v3, saddr(&Vi[row * QP + col]));
                        mma16(acc[i][2 * jp],     aP[kl], v0, v1);
                        mma16(acc[i][2 * jp + 1], aP[kl], v2, v3);
                    }
                    unsigned u0, u1;
                    ldsm2(u0, u1, saddr(&Vi[(32 + (lane & 7)) * QP + 16 * kk + ((lane & 8) ? 8 : 0)]));
                    mma16(accl[i], aP[kl], u0, u1);
                }
            }
        }
    }

    // Epilogue: l lives at n-col 0 of the l-block (tg==0 threads); broadcast in quad
    __syncthreads();
    float* Os = (float*)sm;  // [32][65] overlay
    float r0[KC], r1[KC];
    const int src = lane & ~3;
#pragma unroll
    for (int i = 0; i < KC; i++) {
        float l0 = __shfl_sync(0xffffffffu, accl[i][0], src);
        float l1 = __shfl_sync(0xffffffffu, accl[i][2], src);
        r0[i] = 1.f / (3.f * l0);
        r1[i] = 1.f / (3.f * l1);
    }
    const int qg = 16 * w + g;
#pragma unroll
    for (int jn = 0; jn < 4; jn++) {
        int d0 = 8 * jn + 2 * tg;
        float o00 = acc[0][jn][0] * r0[0] + acc[1][jn][0] * r0[1] + acc[2][jn][0] * r0[2];
        float o01 = acc[0][jn][1] * r0[0] + acc[1][jn][1] * r0[1] + acc[2][jn][1] * r0[2];
        float o10 = acc[0][jn][2] * r1[0] + acc[1][jn][2] * r1[1] + acc[2][jn][2] * r1[2];
        float o11 = acc[0][jn][3] * r1[0] + acc[1][jn][3] * r1[1] + acc[2][jn][3] * r1[2];
        Os[d0 * 65 + qg]           = o00;
        Os[(d0 + 1) * 65 + qg]     = o01;
        Os[d0 * 65 + qg + 8]       = o10;
        Os[(d0 + 1) * 65 + qg + 8] = o11;
    }
    __syncthreads();
    float* ob = g_att + (size_t)(b * C2 + h * DD) * NN;
#pragma unroll
    for (int j = 0; j < 16; j++) {
        int i = t + 128 * j, d = i >> 6, q = i & 63;
        ob[(size_t)d * NN + q0 + q] = Os[d * 65 + q];
    }
}

// ---------------------------------------------------------------------------
extern "C" void kernel_launch(void* const* d_in, const int* in_sizes, int n_in,
                              void* d_out, int out_size)
{
    const float* x         = (const float*)d_in[0];
    const float* W_in      = (const float*)d_in[1];
    const float* W_cluster = (const float*)d_in[2];
    const float* b_cluster = (const float*)d_in[3];
    const float* W_qkv     = (const float*)d_in[4];
    const float* W_proj    = (const float*)d_in[5];
    float* out = (float*)d_out;

    float *xf, *qkv, *att;
    cudaGetSymbolAddress((void**)&xf,  g_xf);
    cudaGetSymbolAddress((void**)&qkv, g_qkv);
    cudaGetSymbolAddress((void**)&att, g_att);

    // proj_in (split-bf16 tensor, near-fp32 — residual identity path)
    gemm_split<<<dim3(NN / 128, C2 / 128, BB), 256>>>(W_in, x, xf, C2, NN, C1);
    // cluster probs
    cluster_kernel<<<dim3(4, BB), 256>>>(W_cluster, b_cluster);
    // qkv (bf16 tensor)
    gemm_bf16<false><<<dim3(NN / 128, 768 / 128, BB), 256>>>(W_qkv, xf, qkv, nullptr, 3 * C2, NN, C2);
    // clustered attention
    attn_kernel<<<dim3(NN / 64, HEADS, BB), 128>>>();
    // proj_out + residual (bf16 tensor, fp32 residual add)
    gemm_bf16<true><<<dim3(NN / 128, C2 / 128, BB), 256>>>(W_proj, att, out, xf, C2, NN, C2);
}

// round 12
// speedup vs baseline: 1.3270x; 1.3270x over previous
#include <cuda_runtime.h>
#include <cuda_bf16.h>

// Problem constants
#define BB 8
#define C1 128
#define C2 256
#define NN 1024
#define HEADS 8
#define DD 32
#define KC 3
#define SCALE 0.17677669529663687f   // 32^-0.5
#define LOG2E 1.4426950408889634f
#define QSC (SCALE * LOG2E)

// Scratch (device globals; no allocation allowed)
__device__ float g_xf[BB * C2 * NN];        // proj_in out / identity [b][c][n]
__device__ float g_prob[BB * KC * NN];      // cluster probs [b][k][n]
__device__ float g_qkv[BB * 3 * C2 * NN];   // qkv [b][o][n]
__device__ float g_att[BB * C2 * NN];       // attention out [b][c][n]

// ---------------------------------------------------------------------------
__device__ __forceinline__ float ex2(float x) {
    float r; asm("ex2.approx.f32 %0, %1;" : "=f"(r) : "f"(x)); return r;
}
__device__ __forceinline__ unsigned pack_bf2(float lo, float hi) {
    unsigned r;
    asm("cvt.rn.bf16x2.f32 %0, %1, %2;" : "=r"(r) : "f"(hi), "f"(lo));
    return r;
}
__device__ __forceinline__ unsigned saddr(const void* p) {
    return (unsigned)__cvta_generic_to_shared(p);
}
__device__ __forceinline__ void ldsm4(unsigned& r0, unsigned& r1, unsigned& r2, unsigned& r3, unsigned a) {
    asm volatile("ldmatrix.sync.aligned.m8n8.x4.shared.b16 {%0,%1,%2,%3}, [%4];"
                 : "=r"(r0), "=r"(r1), "=r"(r2), "=r"(r3) : "r"(a));
}
__device__ __forceinline__ void ldsm4t(unsigned& r0, unsigned& r1, unsigned& r2, unsigned& r3, unsigned a) {
    asm volatile("ldmatrix.sync.aligned.m8n8.x4.trans.shared.b16 {%0,%1,%2,%3}, [%4];"
                 : "=r"(r0), "=r"(r1), "=r"(r2), "=r"(r3) : "r"(a));
}
__device__ __forceinline__ void mma16(float* c, const unsigned* a, unsigned b0, unsigned b1) {
    asm volatile(
        "mma.sync.aligned.m16n8k16.row.col.f32.bf16.bf16.f32 "
        "{%0,%1,%2,%3}, {%4,%5,%6,%7}, {%8,%9}, {%0,%1,%2,%3};"
        : "+f"(c[0]), "+f"(c[1]), "+f"(c[2]), "+f"(c[3])
        : "r"(a[0]), "r"(a[1]), "r"(a[2]), "r"(a[3]), "r"(b0), "r"(b1));
}

// ---------------------------------------------------------------------------
// fp32 SIMT GEMM (proj_in: feeds the residual identity path)
// ---------------------------------------------------------------------------
__global__ __launch_bounds__(256) void gemm128(
    const float* __restrict__ A, const float* __restrict__ Bmat,
    float* __restrict__ C, int M, int N, int K)
{
    const int n0 = blockIdx.x * 128;
    const int m0 = blockIdx.y * 128;
    const int bz = blockIdx.z;
    Bmat += (size_t)bz * K * N;
    C    += (size_t)bz * M * N;

    __shared__ float As[8][132];
    __shared__ float Bs[8][128];

    const int t  = threadIdx.x;
    const int tx = t & 15;
    const int ty = t >> 4;
    const int am = t >> 1;
    const int ak = (t & 1) * 4;
    const int bk = t >> 5;
    const int bn = (t & 31) * 4;

    float acc[8][8];
#pragma unroll
    for (int i = 0; i < 8; i++)
#pragma unroll
        for (int j = 0; j < 8; j++) acc[i][j] = 0.f;

    for (int kt = 0; kt < K; kt += 8) {
        float4 av = *(const float4*)&A[(size_t)(m0 + am) * K + kt + ak];
        float4 bv = *(const float4*)&Bmat[(size_t)(kt + bk) * N + n0 + bn];
        __syncthreads();
        As[ak + 0][am] = av.x;
        As[ak + 1][am] = av.y;
        As[ak + 2][am] = av.z;
        As[ak + 3][am] = av.w;
        *(float4*)&Bs[bk][bn] = bv;
        __syncthreads();
#pragma unroll
        for (int kk = 0; kk < 8; kk++) {
            float a[8], b[8];
#pragma unroll
            for (int i = 0; i < 8; i++) a[i] = As[kk][ty + 16 * i];
#pragma unroll
            for (int j = 0; j < 8; j++) b[j] = Bs[kk][tx + 16 * j];
#pragma unroll
            for (int i = 0; i < 8; i++)
#pragma unroll
                for (int j = 0; j < 8; j++) acc[i][j] += a[i] * b[j];
        }
    }
#pragma unroll
    for (int i = 0; i < 8; i++)
#pragma unroll
        for (int j = 0; j < 8; j++)
            C[(size_t)(m0 + ty + 16 * i) * N + n0 + tx + 16 * j] = acc[i][j];
}

// ---------------------------------------------------------------------------
// bf16 tensor-core GEMM: C[bz] = A(MxK)@B[bz](KxN) (+Res[bz])
// ---------------------------------------------------------------------------
template <bool ADD_RES>
__global__ __launch_bounds__(256, 2) void gemm_bf16(
    const float* __restrict__ A, const float* __restrict__ Bmat,
    float* __restrict__ C, const float* __restrict__ Res,
    int M, int N, int K)
{
    const int n0 = blockIdx.x * 128;
    const int m0 = blockIdx.y * 128;
    const int bz = blockIdx.z;
    Bmat += (size_t)bz * K * N;
    C    += (size_t)bz * M * N;
    const float* R = ADD_RES ? (Res + (size_t)bz * M * N) : nullptr;

    __shared__ __align__(16) __nv_bfloat16 As[128][40];
    __shared__ __align__(16) __nv_bfloat16 Bs[32][136];

    const int t    = threadIdx.x;
    const int lane = t & 31;
    const int w    = t >> 5;
    const int g    = lane >> 2;
    const int tg   = lane & 3;
    const int wm   = (w >> 2) * 64;
    const int wn   = (w & 3) * 32;

    float acc[4][4][4];
#pragma unroll
    for (int mb = 0; mb < 4; mb++)
#pragma unroll
        for (int nb = 0; nb < 4; nb++)
#pragma unroll
            for (int e = 0; e < 4; e++) acc[mb][nb][e] = 0.f;

    const int lam = t >> 3, lak = (t & 7) * 4;
    const int lbk = t >> 5, lbn = (t & 31) * 4;

    for (int kt = 0; kt < K; kt += 32) {
        __syncthreads();
#pragma unroll
        for (int p = 0; p < 4; p++) {
            float4 v = *(const float4*)&A[(size_t)(m0 + lam + 32 * p) * K + kt + lak];
            *(unsigned*)&As[lam + 32 * p][lak]     = pack_bf2(v.x, v.y);
            *(unsigned*)&As[lam + 32 * p][lak + 2] = pack_bf2(v.z, v.w);
        }
#pragma unroll
        for (int p = 0; p < 4; p++) {
            float4 v = *(const float4*)&Bmat[(size_t)(kt + lbk + 8 * p) * N + n0 + lbn];
            *(unsigned*)&Bs[lbk + 8 * p][lbn]     = pack_bf2(v.x, v.y);
            *(unsigned*)&Bs[lbk + 8 * p][lbn + 2] = pack_bf2(v.z, v.w);
        }
        __syncthreads();
#pragma unroll
        for (int ks = 0; ks < 2; ks++) {
            unsigned a[4][4], bb[2][4];
#pragma unroll
            for (int mb = 0; mb < 4; mb++) {
                int row = wm + 16 * mb + (lane & 7) + ((lane & 8) ? 8 : 0);
                int col = 16 * ks + ((lane >= 16) ? 8 : 0);
                ldsm4(a[mb][0], a[mb][1], a[mb][2], a[mb][3], saddr(&As[row][col]));
            }
#pragma unroll
            for (int np = 0; np < 2; np++) {
                int row = 16 * ks + (lane & 7) + ((lane & 8) ? 8 : 0);
                int col = wn + 16 * np + ((lane >= 16) ? 8 : 0);
                ldsm4t(bb[np][0], bb[np][1], bb[np][2], bb[np][3], saddr(&Bs[row][col]));
            }
#pragma unroll
            for (int mb = 0; mb < 4; mb++)
#pragma unroll
                for (int nb = 0; nb < 4; nb++)
                    mma16(acc[mb][nb], a[mb], bb[nb >> 1][(nb & 1) * 2], bb[nb >> 1][(nb & 1) * 2 + 1]);
        }
    }

#pragma unroll
    for (int mb = 0; mb < 4; mb++) {
        const int mr = m0 + wm + 16 * mb;
#pragma unroll
        for (int nb = 0; nb < 4; nb++) {
            const int nc = n0 + wn + 8 * nb + 2 * tg;
            const size_t i0 = (size_t)(mr + g) * N + nc;
            const size_t i1 = (size_t)(mr + g + 8) * N + nc;
            float2 v0 = make_float2(acc[mb][nb][0], acc[mb][nb][1]);
            float2 v1 = make_float2(acc[mb][nb][2], acc[mb][nb][3]);
            if (ADD_RES) {
                float2 r0 = *(const float2*)&R[i0];
                float2 r1 = *(const float2*)&R[i1];
                v0.x += r0.x; v0.y += r0.y; v1.x += r1.x; v1.y += r1.y;
            }
            *(float2*)&C[i0] = v0;
            *(float2*)&C[i1] = v1;
        }
    }
}

// ---------------------------------------------------------------------------
// Cluster logits + softmax over KC=3
// ---------------------------------------------------------------------------
__global__ __launch_bounds__(256) void cluster_kernel(
    const float* __restrict__ Wc, const float* __restrict__ bc)
{
    const int b = blockIdx.y;
    const int n = blockIdx.x * 256 + threadIdx.x;

    __shared__ float Wcs[KC][C2];
    __shared__ float bcs[KC];
    for (int i = threadIdx.x; i < KC * C2; i += 256) Wcs[i / C2][i % C2] = Wc[i];
    if (threadIdx.x < KC) bcs[threadIdx.x] = bc[threadIdx.x];
    __syncthreads();

    const float* xb = g_xf + (size_t)b * C2 * NN;
    float a0 = bcs[0], a1 = bcs[1], a2 = bcs[2];
#pragma unroll 4
    for (int c = 0; c < C2; c++) {
        float xv = xb[(size_t)c * NN + n];
        a0 += Wcs[0][c] * xv;
        a1 += Wcs[1][c] * xv;
        a2 += Wcs[2][c] * xv;
    }
    float mm = fmaxf(a0, fmaxf(a1, a2));
    float e0 = __expf(a0 - mm), e1 = __expf(a1 - mm), e2 = __expf(a2 - mm);
    float inv = 1.f / (e0 + e1 + e2);
    g_prob[(size_t)(b * KC + 0) * NN + n] = e0 * inv;
    g_prob[(size_t)(b * KC + 1) * NN + n] = e1 * inv;
    g_prob[(size_t)(b * KC + 2) * NN + n] = e2 * inv;
}

// ---------------------------------------------------------------------------
// Clustered attention (round-5 structure, register-trimmed).
// 128 threads (4 warps), q-tile 64 (warp w: rows 16w..16w+15), k-tile 64
// processed as two 32-key chunks (S regs halved). Raw shared K/V tiles;
// S = Q@K^T once; 3 no-max exp2 softmaxes; P (x pk) packed straight into
// mma A-fragments; PV via mma with ldsm V frags.
// ---------------------------------------------------------------------------
#define QP 72  // bf16 pitch
__global__ __launch_bounds__(128, 4) void attn_kernel()
{
    const int q0 = blockIdx.x * 64;
    const int h  = blockIdx.y;
    const int b  = blockIdx.z;
    const int t    = threadIdx.x;
    const int lane = t & 31;
    const int w    = t >> 5;
    const int g    = lane >> 2;
    const int tg   = lane & 3;

    __shared__ __align__(16) char sm[14592];
    __nv_bfloat16* Qds = (__nv_bfloat16*)(sm);          // [32][72] raw q
    __nv_bfloat16* Kds = (__nv_bfloat16*)(sm + 4608);   // [32][72] raw k
    __nv_bfloat16* Vds = (__nv_bfloat16*)(sm + 9216);   // [32][72] raw v
    float* probKs      = (float*)(sm + 13824);          // [3][64]
    float* Os          = (float*)sm;                    // [32][65] epilogue overlay

    const float* qb = g_qkv + (size_t)(b * 768 + h * DD) * NN;
    const float* kb = qb + (size_t)256 * NN;
    const float* vb = qb + (size_t)512 * NN;
    const float* pb = g_prob + (size_t)b * KC * NN;

    const int ld  = t >> 4;         // 0..7
    const int lt4 = (t & 15) * 4;   // 0..60

    // Q tile: [d][tok] f32 -> bf16
#pragma unroll
    for (int p = 0; p < 4; p++) {
        float4 v = *(const float4*)&qb[(size_t)(ld + 8 * p) * NN + q0 + lt4];
        *(uint2*)&Qds[(ld + 8 * p) * QP + lt4] =
            make_uint2(pack_bf2(v.x, v.y), pack_bf2(v.z, v.w));
    }
    __syncthreads();

    // Q fragments (loop invariant)
    unsigned aQ[2][4];
#pragma unroll
    for (int ds = 0; ds < 2; ds++) {
        int row = 16 * ds + (lane & 7) + ((lane >= 16) ? 8 : 0);
        int col = 16 * w + ((lane & 8) ? 8 : 0);
        ldsm4t(aQ[ds][0], aQ[ds][1], aQ[ds][2], aQ[ds][3], saddr(&Qds[row * QP + col]));
    }
    // per-row cluster q coefficients (gmem, once)
    float qc[KC][2];
#pragma unroll
    for (int i = 0; i < KC; i++) {
        qc[i][0] = pb[(size_t)i * NN + q0 + 16 * w + g]     * QSC;
        qc[i][1] = pb[(size_t)i * NN + q0 + 16 * w + g + 8] * QSC;
    }

    float acc[KC][4][4];
    float lacc[KC][2];
#pragma unroll
    for (int i = 0; i < KC; i++) {
        lacc[i][0] = 0.f; lacc[i][1] = 0.f;
#pragma unroll
        for (int jn = 0; jn < 4; jn++)
#pragma unroll
            for (int e = 0; e < 4; e++) acc[i][jn][e] = 0.f;
    }

    for (int k0 = 0; k0 < NN; k0 += 64) {
        __syncthreads();
#pragma unroll
        for (int p = 0; p < 4; p++) {
            const int row = ld + 8 * p;
            float4 kv = *(const float4*)&kb[(size_t)row * NN + k0 + lt4];
            float4 vv = *(const float4*)&vb[(size_t)row * NN + k0 + lt4];
            *(uint2*)&Kds[row * QP + lt4] = make_uint2(pack_bf2(kv.x, kv.y), pack_bf2(kv.z, kv.w));
            *(uint2*)&Vds[row * QP + lt4] = make_uint2(pack_bf2(vv.x, vv.y), pack_bf2(vv.z, vv.w));
        }
        if (t < KC * 64) probKs[t] = pb[(size_t)(t >> 6) * NN + k0 + (t & 63)];
        __syncthreads();

#pragma unroll
        for (int ch = 0; ch < 2; ch++) {
            // S chunk [16 x 32] = Q @ K^T (raw), keys ch*32 .. ch*32+31
            float S[4][4];
#pragma unroll
            for (int j = 0; j < 4; j++)
#pragma unroll
                for (int e = 0; e < 4; e++) S[j][e] = 0.f;
#pragma unroll
            for (int ds = 0; ds < 2; ds++) {
#pragma unroll
                for (int jl = 0; jl < 2; jl++) {
                    const int jp = 2 * ch + jl;
                    unsigned b0a, b1a, b0b, b1b;
                    int row = 16 * ds + (lane & 7) + ((lane & 8) ? 8 : 0);
                    int col = 16 * jp + ((lane >= 16) ? 8 : 0);
                    ldsm4t(b0a, b1a, b0b, b1b, saddr(&Kds[row * QP + col]));
                    mma16(S[2 * jl],     aQ[ds], b0a, b1a);
                    mma16(S[2 * jl + 1], aQ[ds], b0b, b1b);
                }
            }
            // 3 clusters: exp2 softmax + PV on this chunk
#pragma unroll
            for (int i = 0; i < KC; i++) {
                const float q0c = qc[i][0], q1c = qc[i][1];
                unsigned aP[2][4];
#pragma unroll
                for (int j = 0; j < 4; j++) {
                    const float2 pk = *(const float2*)&probKs[i * 64 + ch * 32 + 8 * j + 2 * tg];
                    float p00 = ex2(q0c * (pk.x * S[j][0]));
                    float p01 = ex2(q0c * (pk.y * S[j][1]));
                    float p10 = ex2(q1c * (pk.x * S[j][2]));
                    float p11 = ex2(q1c * (pk.y * S[j][3]));
                    lacc[i][0] += p00 + p01;
                    lacc[i][1] += p10 + p11;
                    aP[j >> 1][(j & 1) * 2]     = pack_bf2(p00 * pk.x, p01 * pk.y);
                    aP[j >> 1][(j & 1) * 2 + 1] = pack_bf2(p10 * pk.x, p11 * pk.y);
                }
#pragma unroll
                for (int kl = 0; kl < 2; kl++) {
                    const int kk = 2 * ch + kl;
#pragma unroll
                    for (int jp = 0; jp < 2; jp++) {
                        unsigned v0, v1, v2, v3;
                        int row = 8 * (2 * jp + ((lane >= 16) ? 1 : 0)) + (lane & 7);
                        int col = 16 * kk + ((lane & 8) ? 8 : 0);
                        ldsm4(v0, v1, v2, v3, saddr(&Vds[row * QP + col]));
                        mma16(acc[i][2 * jp],     aP[kl], v0, v1);
                        mma16(acc[i][2 * jp + 1], aP[kl], v2, v3);
                    }
                }
            }
        }
    }

    // Epilogue: reduce l over quad, combine clusters, stage [d][q], write out
    __syncthreads();
    float r0[KC], r1[KC];
#pragma unroll
    for (int i = 0; i < KC; i++) {
        float l0 = lacc[i][0];
        l0 += __shfl_xor_sync(0xffffffffu, l0, 1);
        l0 += __shfl_xor_sync(0xffffffffu, l0, 2);
        float l1 = lacc[i][1];
        l1 += __shfl_xor_sync(0xffffffffu, l1, 1);
        l1 += __shfl_xor_sync(0xffffffffu, l1, 2);
        r0[i] = 1.f / (3.f * l0);
        r1[i] = 1.f / (3.f * l1);
    }
    const int qg = 16 * w + g;
#pragma unroll
    for (int jn = 0; jn < 4; jn++) {
        int d0 = 8 * jn + 2 * tg;
        float o00 = acc[0][jn][0] * r0[0] + acc[1][jn][0] * r0[1] + acc[2][jn][0] * r0[2];
        float o01 = acc[0][jn][1] * r0[0] + acc[1][jn][1] * r0[1] + acc[2][jn][1] * r0[2];
        float o10 = acc[0][jn][2] * r1[0] + acc[1][jn][2] * r1[1] + acc[2][jn][2] * r1[2];
        float o11 = acc[0][jn][3] * r1[0] + acc[1][jn][3] * r1[1] + acc[2][jn][3] * r1[2];
        Os[d0 * 65 + qg]           = o00;
        Os[(d0 + 1) * 65 + qg]     = o01;
        Os[d0 * 65 + qg + 8]       = o10;
        Os[(d0 + 1) * 65 + qg + 8] = o11;
    }
    __syncthreads();
    float* ob = g_att + (size_t)(b * C2 + h * DD) * NN;
#pragma unroll
    for (int j = 0; j < 16; j++) {
        int i = t + 128 * j, d = i >> 6, q = i & 63;
        ob[(size_t)d * NN + q0 + q] = Os[d * 65 + q];
    }
}

// ---------------------------------------------------------------------------
extern "C" void kernel_launch(void* const* d_in, const int* in_sizes, int n_in,
                              void* d_out, int out_size)
{
    const float* x         = (const float*)d_in[0];
    const float* W_in      = (const float*)d_in[1];
    const float* W_cluster = (const float*)d_in[2];
    const float* b_cluster = (const float*)d_in[3];
    const float* W_qkv     = (const float*)d_in[4];
    const float* W_proj    = (const float*)d_in[5];
    float* out = (float*)d_out;

    float *xf, *qkv, *att;
    cudaGetSymbolAddress((void**)&xf,  g_xf);
    cudaGetSymbolAddress((void**)&qkv, g_qkv);
    cudaGetSymbolAddress((void**)&att, g_att);

    // proj_in (fp32 SIMT — residual identity path)
    gemm128<<<dim3(NN / 128, C2 / 128, BB), 256>>>(W_in, x, xf, C2, NN, C1);
    // cluster probs
    cluster_kernel<<<dim3(4, BB), 256>>>(W_cluster, b_cluster);
    // qkv (bf16 tensor)
    gemm_bf16<false><<<dim3(NN / 128, 768 / 128, BB), 256>>>(W_qkv, xf, qkv, nullptr, 3 * C2, NN, C2);
    // clustered attention
    attn_kernel<<<dim3(NN / 64, HEADS, BB), 128>>>();
    // proj_out + residual (bf16 tensor, fp32 residual add)
    gemm_bf16<true><<<dim3(NN / 128, C2 / 128, BB), 256>>>(W_proj, att, out, xf, C2, NN, C2);
}

// round 15
// speedup vs baseline: 1.4258x; 1.0745x over previous
#include <cuda_runtime.h>
#include <cuda_bf16.h>

// Problem constants
#define BB 8
#define C1 128
#define C2 256
#define NN 1024
#define HEADS 8
#define DD 32
#define KC 3
#define SCALE 0.17677669529663687f   // 32^-0.5
#define LOG2E 1.4426950408889634f
#define QSC (SCALE * LOG2E)

// Scratch (device globals; no allocation allowed)
__device__ float g_xf[BB * C2 * NN];              // proj_in out / identity [b][c][n]
__device__ float g_prob[BB * KC * NN];            // cluster probs [b][k][n]
__device__ __nv_bfloat16 g_qkvh[BB * 3 * C2 * NN];// qkv bf16 [b][o][n]
__device__ float g_att[BB * C2 * NN];             // attention out [b][c][n]

// ---------------------------------------------------------------------------
__device__ __forceinline__ float ex2(float x) {
    float r; asm("ex2.approx.f32 %0, %1;" : "=f"(r) : "f"(x)); return r;
}
__device__ __forceinline__ unsigned pack_bf2(float lo, float hi) {
    unsigned r;
    asm("cvt.rn.bf16x2.f32 %0, %1, %2;" : "=r"(r) : "f"(hi), "f"(lo));
    return r;
}
__device__ __forceinline__ unsigned saddr(const void* p) {
    return (unsigned)__cvta_generic_to_shared(p);
}
__device__ __forceinline__ void cpa16(unsigned dst, const void* src) {
    asm volatile("cp.async.cg.shared.global [%0], [%1], 16;" :: "r"(dst), "l"(src));
}
__device__ __forceinline__ void cp_commit() {
    asm volatile("cp.async.commit_group;");
}
template <int N>
__device__ __forceinline__ void cp_wait() {
    asm volatile("cp.async.wait_group %0;" :: "n"(N));
}
__device__ __forceinline__ void ldsm4(unsigned& r0, unsigned& r1, unsigned& r2, unsigned& r3, unsigned a) {
    asm volatile("ldmatrix.sync.aligned.m8n8.x4.shared.b16 {%0,%1,%2,%3}, [%4];"
                 : "=r"(r0), "=r"(r1), "=r"(r2), "=r"(r3) : "r"(a));
}
__device__ __forceinline__ void ldsm4t(unsigned& r0, unsigned& r1, unsigned& r2, unsigned& r3, unsigned a) {
    asm volatile("ldmatrix.sync.aligned.m8n8.x4.trans.shared.b16 {%0,%1,%2,%3}, [%4];"
                 : "=r"(r0), "=r"(r1), "=r"(r2), "=r"(r3) : "r"(a));
}
__device__ __forceinline__ void mma16(float* c, const unsigned* a, unsigned b0, unsigned b1) {
    asm volatile(
        "mma.sync.aligned.m16n8k16.row.col.f32.bf16.bf16.f32 "
        "{%0,%1,%2,%3}, {%4,%5,%6,%7}, {%8,%9}, {%0,%1,%2,%3};"
        : "+f"(c[0]), "+f"(c[1]), "+f"(c[2]), "+f"(c[3])
        : "r"(a[0]), "r"(a[1]), "r"(a[2]), "r"(a[3]), "r"(b0), "r"(b1));
}

// ---------------------------------------------------------------------------
// fp32 SIMT GEMM (proj_in: feeds the residual identity path)
// ---------------------------------------------------------------------------
__global__ __launch_bounds__(256) void gemm128(
    const float* __restrict__ A, const float* __restrict__ Bmat,
    float* __restrict__ C, int M, int N, int K)
{
    const int n0 = blockIdx.x * 128;
    const int m0 = blockIdx.y * 128;
    const int bz = blockIdx.z;
    Bmat += (size_t)bz * K * N;
    C    += (size_t)bz * M * N;

    __shared__ float As[8][132];
    __shared__ float Bs[8][128];

    const int t  = threadIdx.x;
    const int tx = t & 15;
    const int ty = t >> 4;
    const int am = t >> 1;
    const int ak = (t & 1) * 4;
    const int bk = t >> 5;
    const int bn = (t & 31) * 4;

    float acc[8][8];
#pragma unroll
    for (int i = 0; i < 8; i++)
#pragma unroll
        for (int j = 0; j < 8; j++) acc[i][j] = 0.f;

    for (int kt = 0; kt < K; kt += 8) {
        float4 av = *(const float4*)&A[(size_t)(m0 + am) * K + kt + ak];
        float4 bv = *(const float4*)&Bmat[(size_t)(kt + bk) * N + n0 + bn];
        __syncthreads();
        As[ak + 0][am] = av.x;
        As[ak + 1][am] = av.y;
        As[ak + 2][am] = av.z;
        As[ak + 3][am] = av.w;
        *(float4*)&Bs[bk][bn] = bv;
        __syncthreads();
#pragma unroll
        for (int kk = 0; kk < 8; kk++) {
            float a[8], b[8];
#pragma unroll
            for (int i = 0; i < 8; i++) a[i] = As[kk][ty + 16 * i];
#pragma unroll
            for (int j = 0; j < 8; j++) b[j] = Bs[kk][tx + 16 * j];
#pragma unroll
            for (int i = 0; i < 8; i++)
#pragma unroll
                for (int j = 0; j < 8; j++) acc[i][j] += a[i] * b[j];
        }
    }
#pragma unroll
    for (int i = 0; i < 8; i++)
#pragma unroll
        for (int j = 0; j < 8; j++)
            C[(size_t)(m0 + ty + 16 * i) * N + n0 + tx + 16 * j] = acc[i][j];
}

// ---------------------------------------------------------------------------
// bf16 tensor-core GEMM. MODE 0: f32 out. MODE 1: f32 + residual. MODE 2:
// bf16 out (C cast to __nv_bfloat16*).
// ---------------------------------------------------------------------------
template <int MODE>
__global__ __launch_bounds__(256, 2) void gemm_bf16(
    const float* __restrict__ A, const float* __restrict__ Bmat,
    float* __restrict__ C, const float* __restrict__ Res,
    int M, int N, int K)
{
    const int n0 = blockIdx.x * 128;
    const int m0 = blockIdx.y * 128;
    const int bz = blockIdx.z;
    Bmat += (size_t)bz * K * N;
    const float* R = (MODE == 1) ? (Res + (size_t)bz * M * N) : nullptr;

    __shared__ __align__(16) __nv_bfloat16 As[128][40];
    __shared__ __align__(16) __nv_bfloat16 Bs[32][136];

    const int t    = threadIdx.x;
    const int lane = t & 31;
    const int w    = t >> 5;
    const int g    = lane >> 2;
    const int tg   = lane & 3;
    const int wm   = (w >> 2) * 64;
    const int wn   = (w & 3) * 32;

    float acc[4][4][4];
#pragma unroll
    for (int mb = 0; mb < 4; mb++)
#pragma unroll
        for (int nb = 0; nb < 4; nb++)
#pragma unroll
            for (int e = 0; e < 4; e++) acc[mb][nb][e] = 0.f;

    const int lam = t >> 3, lak = (t & 7) * 4;
    const int lbk = t >> 5, lbn = (t & 31) * 4;

    for (int kt = 0; kt < K; kt += 32) {
        __syncthreads();
#pragma unroll
        for (int p = 0; p < 4; p++) {
            float4 v = *(const float4*)&A[(size_t)(m0 + lam + 32 * p) * K + kt + lak];
            *(unsigned*)&As[lam + 32 * p][lak]     = pack_bf2(v.x, v.y);
            *(unsigned*)&As[lam + 32 * p][lak + 2] = pack_bf2(v.z, v.w);
        }
#pragma unroll
        for (int p = 0; p < 4; p++) {
            float4 v = *(const float4*)&Bmat[(size_t)(kt + lbk + 8 * p) * N + n0 + lbn];
            *(unsigned*)&Bs[lbk + 8 * p][lbn]     = pack_bf2(v.x, v.y);
            *(unsigned*)&Bs[lbk + 8 * p][lbn + 2] = pack_bf2(v.z, v.w);
        }
        __syncthreads();
#pragma unroll
        for (int ks = 0; ks < 2; ks++) {
            unsigned a[4][4], bb[2][4];
#pragma unroll
            for (int mb = 0; mb < 4; mb++) {
                int row = wm + 16 * mb + (lane & 7) + ((lane & 8) ? 8 : 0);
                int col = 16 * ks + ((lane >= 16) ? 8 : 0);
                ldsm4(a[mb][0], a[mb][1], a[mb][2], a[mb][3], saddr(&As[row][col]));
            }
#pragma unroll
            for (int np = 0; np < 2; np++) {
                int row = 16 * ks + (lane & 7) + ((lane & 8) ? 8 : 0);
                int col = wn + 16 * np + ((lane >= 16) ? 8 : 0);
                ldsm4t(bb[np][0], bb[np][1], bb[np][2], bb[np][3], saddr(&Bs[row][col]));
            }
#pragma unroll
            for (int mb = 0; mb < 4; mb++)
#pragma unroll
                for (int nb = 0; nb < 4; nb++)
                    mma16(acc[mb][nb], a[mb], bb[nb >> 1][(nb & 1) * 2], bb[nb >> 1][(nb & 1) * 2 + 1]);
        }
    }

    if (MODE == 2) {
        __nv_bfloat16* Cb = (__nv_bfloat16*)C + (size_t)bz * M * N;
#pragma unroll
        for (int mb = 0; mb < 4; mb++) {
            const int mr = m0 + wm + 16 * mb;
#pragma unroll
            for (int nb = 0; nb < 4; nb++) {
                const int nc = n0 + wn + 8 * nb + 2 * tg;
                *(unsigned*)&Cb[(size_t)(mr + g) * N + nc]     = pack_bf2(acc[mb][nb][0], acc[mb][nb][1]);
                *(unsigned*)&Cb[(size_t)(mr + g + 8) * N + nc] = pack_bf2(acc[mb][nb][2], acc[mb][nb][3]);
            }
        }
        return;
    }

    float* Cb = C + (size_t)bz * M * N;
#pragma unroll
    for (int mb = 0; mb < 4; mb++) {
        const int mr = m0 + wm + 16 * mb;
#pragma unroll
        for (int nb = 0; nb < 4; nb++) {
            const int nc = n0 + wn + 8 * nb + 2 * tg;
            const size_t i0 = (size_t)(mr + g) * N + nc;
            const size_t i1 = (size_t)(mr + g + 8) * N + nc;
            float2 v0 = make_float2(acc[mb][nb][0], acc[mb][nb][1]);
            float2 v1 = make_float2(acc[mb][nb][2], acc[mb][nb][3]);
            if (MODE == 1) {
                float2 r0 = *(const float2*)&R[i0];
                float2 r1 = *(const float2*)&R[i1];
                v0.x += r0.x; v0.y += r0.y; v1.x += r1.x; v1.y += r1.y;
            }
            *(float2*)&Cb[i0] = v0;
            *(float2*)&Cb[i1] = v1;
        }
    }
}

// ---------------------------------------------------------------------------
// Cluster logits + softmax over KC=3
// ---------------------------------------------------------------------------
__global__ __launch_bounds__(256) void cluster_kernel(
    const float* __restrict__ Wc, const float* __restrict__ bc)
{
    const int b = blockIdx.y;
    const int n = blockIdx.x * 256 + threadIdx.x;

    __shared__ float Wcs[KC][C2];
    __shared__ float bcs[KC];
    for (int i = threadIdx.x; i < KC * C2; i += 256) Wcs[i / C2][i % C2] = Wc[i];
    if (threadIdx.x < KC) bcs[threadIdx.x] = bc[threadIdx.x];
    __syncthreads();

    const float* xb = g_xf + (size_t)b * C2 * NN;
    float a0 = bcs[0], a1 = bcs[1], a2 = bcs[2];
#pragma unroll 4
    for (int c = 0; c < C2; c++) {
        float xv = xb[(size_t)c * NN + n];
        a0 += Wcs[0][c] * xv;
        a1 += Wcs[1][c] * xv;
        a2 += Wcs[2][c] * xv;
    }
    float mm = fmaxf(a0, fmaxf(a1, a2));
    float e0 = __expf(a0 - mm), e1 = __expf(a1 - mm), e2 = __expf(a2 - mm);
    float inv = 1.f / (e0 + e1 + e2);
    g_prob[(size_t)(b * KC + 0) * NN + n] = e0 * inv;
    g_prob[(size_t)(b * KC + 1) * NN + n] = e1 * inv;
    g_prob[(size_t)(b * KC + 2) * NN + n] = e2 * inv;
}

// ---------------------------------------------------------------------------
// Clustered attention: bf16 inputs from g_qkvh, cp.async double-buffered
// K/V/probK tiles, S = Q@K^T once, 3 no-max exp2 softmaxes, register P, PV mma.
// 128 threads (4 warps), q-tile 64, k-tile 64 in two 32-key chunks.
// ---------------------------------------------------------------------------
#define QP 72  // bf16 pitch (144 B/row, 16B-aligned)
// smem map (bytes): Q 0..4608 | K0 4608 | K1 9216 | V0 13824 | V1 18432 |
//                   probK0 23040 (768B) | probK1 23808 | total 24576
__global__ __launch_bounds__(128, 4) void attn_kernel()
{
    const int q0 = blockIdx.x * 64;
    const int h  = blockIdx.y;
    const int b  = blockIdx.z;
    const int t    = threadIdx.x;
    const int lane = t & 31;
    const int w    = t >> 5;
    const int g    = lane >> 2;
    const int tg   = lane & 3;

    __shared__ __align__(16) char sm[24576];

    const __nv_bfloat16* qb = g_qkvh + (size_t)(b * 768 + h * DD) * NN;
    const __nv_bfloat16* kb = qb + (size_t)256 * NN;
    const __nv_bfloat16* vb = qb + (size_t)512 * NN;
    const float* pb = g_prob + (size_t)b * KC * NN;

    // per-row cluster q coefficients (independent LDGs, issue early)
    float qc[KC][2];
#pragma unroll
    for (int i = 0; i < KC; i++) {
        qc[i][0] = pb[(size_t)i * NN + q0 + 16 * w + g]     * QSC;
        qc[i][1] = pb[(size_t)i * NN + q0 + 16 * w + g + 8] * QSC;
    }

    // cp.async mapping: r = row (0..31), c*8 = token chunk
    const int r  = t >> 2;
    const int c0 = (t & 3) * 2;

    // Prologue: Q tile + tile 0 (K0,V0,probK0), one group
    {
        cpa16(saddr(sm + r * 144 + c0 * 16),      qb + (size_t)r * NN + q0 + c0 * 8);
        cpa16(saddr(sm + r * 144 + c0 * 16 + 16), qb + (size_t)r * NN + q0 + c0 * 8 + 8);
        cpa16(saddr(sm + 4608 + r * 144 + c0 * 16),      kb + (size_t)r * NN + c0 * 8);
        cpa16(saddr(sm + 4608 + r * 144 + c0 * 16 + 16), kb + (size_t)r * NN + c0 * 8 + 8);
        cpa16(saddr(sm + 13824 + r * 144 + c0 * 16),      vb + (size_t)r * NN + c0 * 8);
        cpa16(saddr(sm + 13824 + r * 144 + c0 * 16 + 16), vb + (size_t)r * NN + c0 * 8 + 8);
        if (t < 48) cpa16(saddr(sm + 23040 + t * 16), pb + (size_t)(t >> 4) * NN + (t & 15) * 4);
        cp_commit();
    }
    cp_wait<0>();
    __syncthreads();

    // Q fragments (loop invariant)
    const __nv_bfloat16* Qds = (const __nv_bfloat16*)sm;
    unsigned aQ[2][4];
#pragma unroll
    for (int ds = 0; ds < 2; ds++) {
        int row = 16 * ds + (lane & 7) + ((lane >= 16) ? 8 : 0);
        int col = 16 * w + ((lane & 8) ? 8 : 0);
        ldsm4t(aQ[ds][0], aQ[ds][1], aQ[ds][2], aQ[ds][3], saddr(&Qds[row * QP + col]));
    }

    float acc[KC][4][4];
    float lacc[KC][2];
#pragma unroll
    for (int i = 0; i < KC; i++) {
        lacc[i][0] = 0.f; lacc[i][1] = 0.f;
#pragma unroll
        for (int jn = 0; jn < 4; jn++)
#pragma unroll
            for (int e = 0; e < 4; e++) acc[i][jn][e] = 0.f;
    }

    for (int kt = 0; kt < 16; kt++) {
        const int cur = kt & 1;
        // prefetch tile kt+1 into the other buffer
        if (kt < 15) {
            const int nk0 = (kt + 1) * 64;
            char* Kb = sm + 4608  + (cur ^ 1) * 4608;
            char* Vb = sm + 13824 + (cur ^ 1) * 4608;
            char* Pb = sm + 23040 + (cur ^ 1) * 768;
            cpa16(saddr(Kb + r * 144 + c0 * 16),      kb + (size_t)r * NN + nk0 + c0 * 8);
            cpa16(saddr(Kb + r * 144 + c0 * 16 + 16), kb + (size_t)r * NN + nk0 + c0 * 8 + 8);
            cpa16(saddr(Vb + r * 144 + c0 * 16),      vb + (size_t)r * NN + nk0 + c0 * 8);
            cpa16(saddr(Vb + r * 144 + c0 * 16 + 16), vb + (size_t)r * NN + nk0 + c0 * 8 + 8);
            if (t < 48) cpa16(saddr(Pb + t * 16), pb + (size_t)(t >> 4) * NN + nk0 + (t & 15) * 4);
            cp_commit();
            cp_wait<1>();   // tile kt done, tile kt+1 may be in flight
        } else {
            cp_wait<0>();
        }
        __syncthreads();

        const __nv_bfloat16* Kds = (const __nv_bfloat16*)(sm + 4608  + cur * 4608);
        const __nv_bfloat16* Vds = (const __nv_bfloat16*)(sm + 13824 + cur * 4608);
        const float* probKs      = (const float*)(sm + 23040 + cur * 768);

#pragma unroll
        for (int ch = 0; ch < 2; ch++) {
            // S chunk [16 x 32] = Q @ K^T (raw)
            float S[4][4];
#pragma unroll
            for (int j = 0; j < 4; j++)
#pragma unroll
                for (int e = 0; e < 4; e++) S[j][e] = 0.f;
#pragma unroll
            for (int ds = 0; ds < 2; ds++) {
#pragma unroll
                for (int jl = 0; jl < 2; jl++) {
                    const int jp = 2 * ch + jl;
                    unsigned b0a, b1a, b0b, b1b;
                    int row = 16 * ds + (lane & 7) + ((lane & 8) ? 8 : 0);
                    int col = 16 * jp + ((lane >= 16) ? 8 : 0);
                    ldsm4t(b0a, b1a, b0b, b1b, saddr(&Kds[row * QP + col]));
                    mma16(S[2 * jl],     aQ[ds], b0a, b1a);
                    mma16(S[2 * jl + 1], aQ[ds], b0b, b1b);
                }
            }
            // 3 clusters: exp2 softmax + PV on this chunk
#pragma unroll
            for (int i = 0; i < KC; i++) {
                const float q0c = qc[i][0], q1c = qc[i][1];
                unsigned aP[2][4];
#pragma unroll
                for (int j = 0; j < 4; j++) {
                    const float2 pk = *(const float2*)&probKs[i * 64 + ch * 32 + 8 * j + 2 * tg];
                    float p00 = ex2(q0c * (pk.x * S[j][0]));
                    float p01 = ex2(q0c * (pk.y * S[j][1]));
                    float p10 = ex2(q1c * (pk.x * S[j][2]));
                    float p11 = ex2(q1c * (pk.y * S[j][3]));
                    lacc[i][0] += p00 + p01;
                    lacc[i][1] += p10 + p11;
                    aP[j >> 1][(j & 1) * 2]     = pack_bf2(p00 * pk.x, p01 * pk.y);
                    aP[j >> 1][(j & 1) * 2 + 1] = pack_bf2(p10 * pk.x, p11 * pk.y);
                }
#pragma unroll
                for (int kl = 0; kl < 2; kl++) {
                    const int kk = 2 * ch + kl;
#pragma unroll
                    for (int jp = 0; jp < 2; jp++) {
                        unsigned v0, v1, v2, v3;
                        int row = 8 * (2 * jp + ((lane >= 16) ? 1 : 0)) + (lane & 7);
                        int col = 16 * kk + ((lane & 8) ? 8 : 0);
                        ldsm4(v0, v1, v2, v3, saddr(&Vds[row * QP + col]));
                        mma16(acc[i][2 * jp],     aP[kl], v0, v1);
                        mma16(acc[i][2 * jp + 1], aP[kl], v2, v3);
                    }
                }
            }
        }
        __syncthreads();  // frees buf[cur] for the prefetch issued at kt+1
    }

    // Epilogue: reduce l over quad, combine clusters, stage [d][q], write out
    float r0[KC], r1[KC];
#pragma unroll
    for (int i = 0; i < KC; i++) {
        float l0 = lacc[i][0];
        l0 += __shfl_xor_sync(0xffffffffu, l0, 1);
        l0 += __shfl_xor_sync(0xffffffffu, l0, 2);
        float l1 = lacc[i][1];
        l1 += __shfl_xor_sync(0xffffffffu, l1, 1);
        l1 += __shfl_xor_sync(0xffffffffu, l1, 2);
        r0[i] = 1.f / (3.f * l0);
        r1[i] = 1.f / (3.f * l1);
    }
    float* Os = (float*)sm;  // [32][65] overlay (Q/K0/K1 region)
    const int qg = 16 * w + g;
#pragma unroll
    for (int jn = 0; jn < 4; jn++) {
        int d0 = 8 * jn + 2 * tg;
        float o00 = acc[0][jn][0] * r0[0] + acc[1][jn][0] * r0[1] + acc[2][jn][0] * r0[2];
        float o01 = acc[0][jn][1] * r0[0] + acc[1][jn][1] * r0[1] + acc[2][jn][1] * r0[2];
        float o10 = acc[0][jn][2] * r1[0] + acc[1][jn][2] * r1[1] + acc[2][jn][2] * r1[2];
        float o11 = acc[0][jn][3] * r1[0] + acc[1][jn][3] * r1[1] + acc[2][jn][3] * r1[2];
        Os[d0 * 65 + qg]           = o00;
        Os[(d0 + 1) * 65 + qg]     = o01;
        Os[d0 * 65 + qg + 8]       = o10;
        Os[(d0 + 1) * 65 + qg + 8] = o11;
    }
    __syncthreads();
    float* ob = g_att + (size_t)(b * C2 + h * DD) * NN;
#pragma unroll
    for (int j = 0; j < 16; j++) {
        int i = t + 128 * j, d = i >> 6, q = i & 63;
        ob[(size_t)d * NN + q0 + q] = Os[d * 65 + q];
    }
}

// ---------------------------------------------------------------------------
extern "C" void kernel_launch(void* const* d_in, const int* in_sizes, int n_in,
                              void* d_out, int out_size)
{
    const float* x         = (const float*)d_in[0];
    const float* W_in      = (const float*)d_in[1];
    const float* W_cluster = (const float*)d_in[2];
    const float* b_cluster = (const float*)d_in[3];
    const float* W_qkv     = (const float*)d_in[4];
    const float* W_proj    = (const float*)d_in[5];
    float* out = (float*)d_out;

    float *xf, *att;
    __nv_bfloat16* qkvh;
    cudaGetSymbolAddress((void**)&xf,   g_xf);
    cudaGetSymbolAddress((void**)&att,  g_att);
    cudaGetSymbolAddress((void**)&qkvh, g_qkvh);

    // proj_in (fp32 SIMT — residual identity path)
    gemm128<<<dim3(NN / 128, C2 / 128, BB), 256>>>(W_in, x, xf, C2, NN, C1);
    // cluster probs
    cluster_kernel<<<dim3(4, BB), 256>>>(W_cluster, b_cluster);
    // qkv (bf16 tensor, bf16 output)
    gemm_bf16<2><<<dim3(NN / 128, 768 / 128, BB), 256>>>(W_qkv, xf, (float*)qkvh, nullptr, 3 * C2, NN, C2);
    // clustered attention
    attn_kernel<<<dim3(NN / 64, HEADS, BB), 128>>>();
    // proj_out + residual (bf16 tensor, fp32 residual add)
    gemm_bf16<1><<<dim3(NN / 128, C2 / 128, BB), 256>>>(W_proj, att, out, xf, C2, NN, C2);
}

// round 17
// speedup vs baseline: 1.6664x; 1.1688x over previous
#include <cuda_runtime.h>
#include <cuda_fp16.h>

// Problem constants
#define BB 8
#define C1 128
#define C2 256
#define NN 1024
#define HEADS 8
#define DD 32
#define KC 3
#define SCALE 0.17677669529663687f   // 32^-0.5
#define LOG2E 1.4426950408889634f
#define QSC (SCALE * LOG2E)

// Scratch (device globals; no allocation allowed)
__device__ float g_xf[BB * C2 * NN];          // proj_in out / identity [b][c][n]
__device__ float2 g_prob[BB * KC * NN];       // cluster probs (pk, log2 pk) [b][k][n]
__device__ __half g_qkvh[BB * 3 * C2 * NN];   // qkv fp16 [b][o][n]
__device__ float g_att[BB * C2 * NN];         // attention out [b][c][n]

// ---------------------------------------------------------------------------
__device__ __forceinline__ unsigned pack_h2(float lo, float hi) {
    unsigned r;
    asm("cvt.rn.f16x2.f32 %0, %1, %2;" : "=r"(r) : "f"(hi), "f"(lo));
    return r;
}
__device__ __forceinline__ unsigned ex2h2(unsigned x) {
    unsigned r; asm("ex2.approx.f16x2 %0, %1;" : "=r"(r) : "r"(x)); return r;
}
__device__ __forceinline__ float rcpf(float x) {
    float r; asm("rcp.approx.f32 %0, %1;" : "=f"(r) : "f"(x)); return r;
}
__device__ __forceinline__ unsigned saddr(const void* p) {
    return (unsigned)__cvta_generic_to_shared(p);
}
__device__ __forceinline__ void cpa16(unsigned dst, const void* src) {
    asm volatile("cp.async.cg.shared.global [%0], [%1], 16;" :: "r"(dst), "l"(src));
}
__device__ __forceinline__ void cp_commit() {
    asm volatile("cp.async.commit_group;");
}
template <int N>
__device__ __forceinline__ void cp_wait() {
    asm volatile("cp.async.wait_group %0;" :: "n"(N));
}
__device__ __forceinline__ void ldsm4(unsigned& r0, unsigned& r1, unsigned& r2, unsigned& r3, unsigned a) {
    asm volatile("ldmatrix.sync.aligned.m8n8.x4.shared.b16 {%0,%1,%2,%3}, [%4];"
                 : "=r"(r0), "=r"(r1), "=r"(r2), "=r"(r3) : "r"(a));
}
__device__ __forceinline__ void ldsm2(unsigned& r0, unsigned& r1, unsigned a) {
    asm volatile("ldmatrix.sync.aligned.m8n8.x2.shared.b16 {%0,%1}, [%2];"
                 : "=r"(r0), "=r"(r1) : "r"(a));
}
__device__ __forceinline__ void ldsm4t(unsigned& r0, unsigned& r1, unsigned& r2, unsigned& r3, unsigned a) {
    asm volatile("ldmatrix.sync.aligned.m8n8.x4.trans.shared.b16 {%0,%1,%2,%3}, [%4];"
                 : "=r"(r0), "=r"(r1), "=r"(r2), "=r"(r3) : "r"(a));
}
__device__ __forceinline__ void mma16(float* c, const unsigned* a, unsigned b0, unsigned b1) {
    asm volatile(
        "mma.sync.aligned.m16n8k16.row.col.f32.f16.f16.f32 "
        "{%0,%1,%2,%3}, {%4,%5,%6,%7}, {%8,%9}, {%0,%1,%2,%3};"
        : "+f"(c[0]), "+f"(c[1]), "+f"(c[2]), "+f"(c[3])
        : "r"(a[0]), "r"(a[1]), "r"(a[2]), "r"(a[3]), "r"(b0), "r"(b1));
}

// ---------------------------------------------------------------------------
// fp32 SIMT GEMM (proj_in: feeds the residual identity path)
// ---------------------------------------------------------------------------
__global__ __launch_bounds__(256) void gemm128(
    const float* __restrict__ A, const float* __restrict__ Bmat,
    float* __restrict__ C, int M, int N, int K)
{
    const int n0 = blockIdx.x * 128;
    const int m0 = blockIdx.y * 128;
    const int bz = blockIdx.z;
    Bmat += (size_t)bz * K * N;
    C    += (size_t)bz * M * N;

    __shared__ float As[8][132];
    __shared__ float Bs[8][128];

    const int t  = threadIdx.x;
    const int tx = t & 15;
    const int ty = t >> 4;
    const int am = t >> 1;
    const int ak = (t & 1) * 4;
    const int bk = t >> 5;
    const int bn = (t & 31) * 4;

    float acc[8][8];
#pragma unroll
    for (int i = 0; i < 8; i++)
#pragma unroll
        for (int j = 0; j < 8; j++) acc[i][j] = 0.f;

    for (int kt = 0; kt < K; kt += 8) {
        float4 av = *(const float4*)&A[(size_t)(m0 + am) * K + kt + ak];
        float4 bv = *(const float4*)&Bmat[(size_t)(kt + bk) * N + n0 + bn];
        __syncthreads();
        As[ak + 0][am] = av.x;
        As[ak + 1][am] = av.y;
        As[ak + 2][am] = av.z;
        As[ak + 3][am] = av.w;
        *(float4*)&Bs[bk][bn] = bv;
        __syncthreads();
#pragma unroll
        for (int kk = 0; kk < 8; kk++) {
            float a[8], b[8];
#pragma unroll
            for (int i = 0; i < 8; i++) a[i] = As[kk][ty + 16 * i];
#pragma unroll
            for (int j = 0; j < 8; j++) b[j] = Bs[kk][tx + 16 * j];
#pragma unroll
            for (int i = 0; i < 8; i++)
#pragma unroll
                for (int j = 0; j < 8; j++) acc[i][j] += a[i] * b[j];
        }
    }
#pragma unroll
    for (int i = 0; i < 8; i++)
#pragma unroll
        for (int j = 0; j < 8; j++)
            C[(size_t)(m0 + ty + 16 * i) * N + n0 + tx + 16 * j] = acc[i][j];
}

// ---------------------------------------------------------------------------
// fp16 tensor-core GEMM. MODE 1: f32 out + residual. MODE 2: fp16 out.
// 128x128 tile, kstep 32, 8 warps (2x4), each warp 64x32 via m16n8k16.
// ---------------------------------------------------------------------------
template <int MODE>
__global__ __launch_bounds__(256, 2) void gemm_f16(
    const float* __restrict__ A, const float* __restrict__ Bmat,
    float* __restrict__ C, const float* __restrict__ Res,
    int M, int N, int K)
{
    const int n0 = blockIdx.x * 128;
    const int m0 = blockIdx.y * 128;
    const int bz = blockIdx.z;
    Bmat += (size_t)bz * K * N;
    const float* R = (MODE == 1) ? (Res + (size_t)bz * M * N) : nullptr;

    __shared__ __align__(16) __half As[128][40];
    __shared__ __align__(16) __half Bs[32][136];

    const int t    = threadIdx.x;
    const int lane = t & 31;
    const int w    = t >> 5;
    const int g    = lane >> 2;
    const int tg   = lane & 3;
    const int wm   = (w >> 2) * 64;
    const int wn   = (w & 3) * 32;

    float acc[4][4][4];
#pragma unroll
    for (int mb = 0; mb < 4; mb++)
#pragma unroll
        for (int nb = 0; nb < 4; nb++)
#pragma unroll
            for (int e = 0; e < 4; e++) acc[mb][nb][e] = 0.f;

    const int lam = t >> 3, lak = (t & 7) * 4;
    const int lbk = t >> 5, lbn = (t & 31) * 4;

    for (int kt = 0; kt < K; kt += 32) {
        __syncthreads();
#pragma unroll
        for (int p = 0; p < 4; p++) {
            float4 v = *(const float4*)&A[(size_t)(m0 + lam + 32 * p) * K + kt + lak];
            *(unsigned*)&As[lam + 32 * p][lak]     = pack_h2(v.x, v.y);
            *(unsigned*)&As[lam + 32 * p][lak + 2] = pack_h2(v.z, v.w);
        }
#pragma unroll
        for (int p = 0; p < 4; p++) {
            float4 v = *(const float4*)&Bmat[(size_t)(kt + lbk + 8 * p) * N + n0 + lbn];
            *(unsigned*)&Bs[lbk + 8 * p][lbn]     = pack_h2(v.x, v.y);
            *(unsigned*)&Bs[lbk + 8 * p][lbn + 2] = pack_h2(v.z, v.w);
        }
        __syncthreads();
#pragma unroll
        for (int ks = 0; ks < 2; ks++) {
            unsigned a[4][4], bb[2][4];
#pragma unroll
            for (int mb = 0; mb < 4; mb++) {
                int row = wm + 16 * mb + (lane & 7) + ((lane & 8) ? 8 : 0);
                int col = 16 * ks + ((lane >= 16) ? 8 : 0);
                ldsm4(a[mb][0], a[mb][1], a[mb][2], a[mb][3], saddr(&As[row][col]));
            }
#pragma unroll
            for (int np = 0; np < 2; np++) {
                int row = 16 * ks + (lane & 7) + ((lane & 8) ? 8 : 0);
                int col = wn + 16 * np + ((lane >= 16) ? 8 : 0);
                ldsm4t(bb[np][0], bb[np][1], bb[np][2], bb[np][3], saddr(&Bs[row][col]));
            }
#pragma unroll
            for (int mb = 0; mb < 4; mb++)
#pragma unroll
                for (int nb = 0; nb < 4; nb++)
                    mma16(acc[mb][nb], a[mb], bb[nb >> 1][(nb & 1) * 2], bb[nb >> 1][(nb & 1) * 2 + 1]);
        }
    }

    if (MODE == 2) {
        __half* Cb = (__half*)C + (size_t)bz * M * N;
#pragma unroll
        for (int mb = 0; mb < 4; mb++) {
            const int mr = m0 + wm + 16 * mb;
#pragma unroll
            for (int nb = 0; nb < 4; nb++) {
                const int nc = n0 + wn + 8 * nb + 2 * tg;
                *(unsigned*)&Cb[(size_t)(mr + g) * N + nc]     = pack_h2(acc[mb][nb][0], acc[mb][nb][1]);
                *(unsigned*)&Cb[(size_t)(mr + g + 8) * N + nc] = pack_h2(acc[mb][nb][2], acc[mb][nb][3]);
            }
        }
        return;
    }

    float* Cb = C + (size_t)bz * M * N;
#pragma unroll
    for (int mb = 0; mb < 4; mb++) {
        const int mr = m0 + wm + 16 * mb;
#pragma unroll
        for (int nb = 0; nb < 4; nb++) {
            const int nc = n0 + wn + 8 * nb + 2 * tg;
            const size_t i0 = (size_t)(mr + g) * N + nc;
            const size_t i1 = (size_t)(mr + g + 8) * N + nc;
            float2 r0 = *(const float2*)&R[i0];
            float2 r1 = *(const float2*)&R[i1];
            *(float2*)&Cb[i0] = make_float2(acc[mb][nb][0] + r0.x, acc[mb][nb][1] + r0.y);
            *(float2*)&Cb[i1] = make_float2(acc[mb][nb][2] + r1.x, acc[mb][nb][3] + r1.y);
        }
    }
}

// ---------------------------------------------------------------------------
// Cluster logits + softmax over KC=3; writes (pk, log2 pk) float2.
// grid (NN/128, BB), 256 thr: 128 tokens x 2 channel halves, smem combine.
// ---------------------------------------------------------------------------
__global__ __launch_bounds__(256) void cluster_kernel(
    const float* __restrict__ Wc, const float* __restrict__ bc)
{
    const int b  = blockIdx.y;
    const int n0 = blockIdx.x * 128;
    const int t  = threadIdx.x;
    const int hf  = t >> 7;       // channel half
    const int tok = t & 127;
    const int n   = n0 + tok;

    __shared__ float Wcs[KC][C2];
    __shared__ float bcs[KC];
    __shared__ float part[KC][128];
    for (int i = t; i < KC * C2; i += 256) Wcs[i / C2][i % C2] = Wc[i];
    if (t < KC) bcs[t] = bc[t];
    __syncthreads();

    const float* xb = g_xf + (size_t)b * C2 * NN;
    const int cbase = hf * 128;
    float a0 = 0.f, a1 = 0.f, a2 = 0.f;
#pragma unroll 4
    for (int c = 0; c < 128; c++) {
        float xv = xb[(size_t)(cbase + c) * NN + n];
        a0 += Wcs[0][cbase + c] * xv;
        a1 += Wcs[1][cbase + c] * xv;
        a2 += Wcs[2][cbase + c] * xv;
    }
    if (hf == 1) {
        part[0][tok] = a0; part[1][tok] = a1; part[2][tok] = a2;
    }
    __syncthreads();
    if (hf == 0) {
        a0 += part[0][tok] + bcs[0];
        a1 += part[1][tok] + bcs[1];
        a2 += part[2][tok] + bcs[2];
        float mm = fmaxf(a0, fmaxf(a1, a2));
        float e0 = __expf(a0 - mm), e1 = __expf(a1 - mm), e2 = __expf(a2 - mm);
        float inv = 1.f / (e0 + e1 + e2);
        float p0 = e0 * inv, p1 = e1 * inv, p2 = e2 * inv;
        g_prob[(size_t)(b * KC + 0) * NN + n] = make_float2(p0, __log2f(p0));
        g_prob[(size_t)(b * KC + 1) * NN + n] = make_float2(p1, __log2f(p1));
        g_prob[(size_t)(b * KC + 2) * NN + n] = make_float2(p2, __log2f(p2));
    }
}

// ---------------------------------------------------------------------------
// Clustered attention, fp16 pipeline:
//  S = Q@K^T once (f16 mma); P' = p*pk computed as ex2h2(qc*pk*S + log2 pk)
//  (pk folded into exponent, f16x2 MUFU -> result IS the mma A fragment);
//  PV with raw V (f16); l = sum p via mma against static recip rows
//  1/pk_i stored as V rows 32..34 (rebuilt per tile from smem pk).
// 128 threads (4 warps), q-tile 64, k-tile 64 in two 32-key chunks,
// cp.async double-buffered K/V/prob tiles.
// ---------------------------------------------------------------------------
#define QP 72  // half pitch (144 B/row)
// smem (bytes): Q 0 (4608) | K 4608 (2x4608) | V 13824 (2x5760, 40 rows) |
//               prob 25344 (2x1536 float2) | total 28416
__global__ __launch_bounds__(128, 4) void attn_kernel()
{
    const int q0 = blockIdx.x * 64;
    const int h  = blockIdx.y;
    const int b  = blockIdx.z;
    const int t    = threadIdx.x;
    const int lane = t & 31;
    const int w    = t >> 5;
    const int g    = lane >> 2;
    const int tg   = lane & 3;

    __shared__ __align__(16) char sm[28416];

    const __half* qb = g_qkvh + (size_t)(b * 768 + h * DD) * NN;
    const __half* kb = qb + (size_t)256 * NN;
    const __half* vb = qb + (size_t)512 * NN;
    const float2* pb = g_prob + (size_t)b * KC * NN;

    // per-row cluster q coefficients
    float qc[KC][2];
#pragma unroll
    for (int i = 0; i < KC; i++) {
        qc[i][0] = pb[(size_t)i * NN + q0 + 16 * w + g].x     * QSC;
        qc[i][1] = pb[(size_t)i * NN + q0 + 16 * w + g + 8].x * QSC;
    }

    // cp.async mapping: r = row (0..31), c0*8 = token chunk (halves: 8 per 16B)
    const int r  = t >> 2;
    const int c0 = (t & 3) * 2;

    // zero V recip-pad rows 35..39 (both buffers, written once)
    for (int idx = t; idx < 2 * 5 * QP; idx += 128) {
        int bf = idx / (5 * QP), rem = idx % (5 * QP);
        *((unsigned short*)(sm + 13824 + bf * 5760) + (35 + rem / QP) * QP + rem % QP) = 0;
    }

    // Prologue: Q tile + tile 0 (K0,V0,prob0)
    {
        cpa16(saddr(sm + r * 144 + c0 * 16),      qb + (size_t)r * NN + q0 + c0 * 8);
        cpa16(saddr(sm + r * 144 + c0 * 16 + 16), qb + (size_t)r * NN + q0 + c0 * 8 + 8);
        cpa16(saddr(sm + 4608 + r * 144 + c0 * 16),      kb + (size_t)r * NN + c0 * 8);
        cpa16(saddr(sm + 4608 + r * 144 + c0 * 16 + 16), kb + (size_t)r * NN + c0 * 8 + 8);
        cpa16(saddr(sm + 13824 + r * 144 + c0 * 16),      vb + (size_t)r * NN + c0 * 8);
        cpa16(saddr(sm + 13824 + r * 144 + c0 * 16 + 16), vb + (size_t)r * NN + c0 * 8 + 8);
        if (t < 96) cpa16(saddr(sm + 25344 + t * 16), pb + (size_t)(t >> 5) * NN + (t & 31) * 2);
        cp_commit();
    }
    cp_wait<0>();
    __syncthreads();

    // Q fragments (loop invariant)
    const __half* Qds = (const __half*)sm;
    unsigned aQ[2][4];
#pragma unroll
    for (int ds = 0; ds < 2; ds++) {
        int row = 16 * ds + (lane & 7) + ((lane >= 16) ? 8 : 0);
        int col = 16 * w + ((lane & 8) ? 8 : 0);
        ldsm4t(aQ[ds][0], aQ[ds][1], aQ[ds][2], aQ[ds][3], saddr(&Qds[row * QP + col]));
    }

    float acc[KC][4][4];
    float accl[KC][4];
#pragma unroll
    for (int i = 0; i < KC; i++) {
#pragma unroll
        for (int e = 0; e < 4; e++) accl[i][e] = 0.f;
#pragma unroll
        for (int jn = 0; jn < 4; jn++)
#pragma unroll
            for (int e = 0; e < 4; e++) acc[i][jn][e] = 0.f;
    }

    for (int kt = 0; kt < 16; kt++) {
        const int cur = kt & 1;
        if (kt < 15) {
            const int nk0 = (kt + 1) * 64;
            char* Kb = sm + 4608  + (cur ^ 1) * 4608;
            char* Vb = sm + 13824 + (cur ^ 1) * 5760;
            char* Pb = sm + 25344 + (cur ^ 1) * 1536;
            cpa16(saddr(Kb + r * 144 + c0 * 16),      kb + (size_t)r * NN + nk0 + c0 * 8);
            cpa16(saddr(Kb + r * 144 + c0 * 16 + 16), kb + (size_t)r * NN + nk0 + c0 * 8 + 8);
            cpa16(saddr(Vb + r * 144 + c0 * 16),      vb + (size_t)r * NN + nk0 + c0 * 8);
            cpa16(saddr(Vb + r * 144 + c0 * 16 + 16), vb + (size_t)r * NN + nk0 + c0 * 8 + 8);
            if (t < 96) cpa16(saddr(Pb + t * 16), pb + (size_t)(t >> 5) * NN + nk0 + (t & 31) * 2);
            cp_commit();
            cp_wait<1>();
        } else {
            cp_wait<0>();
        }

        __half* Vh           = (__half*)(sm + 13824 + cur * 5760);
        const __half* Kds    = (const __half*)(sm + 4608 + cur * 4608);
        const float* probKs  = (const float*)(sm + 25344 + cur * 1536);  // float2 data

        // build recip rows 32..34 of V (l-trick): row 32+i = 1/pk_i
        if (t < 96) {
            const int row = t >> 5;        // cluster
            const int kp  = (t & 31) * 2;  // key pair
            float4 pv = *(const float4*)&probKs[(row * 64 + kp) * 2];
            *(unsigned*)&Vh[(32 + row) * QP + kp] = pack_h2(rcpf(pv.x), rcpf(pv.z));
        }
        __syncthreads();

#pragma unroll
        for (int ch = 0; ch < 2; ch++) {
            // S chunk [16 x 32] = Q @ K^T (raw)
            float S[4][4];
#pragma unroll
            for (int j = 0; j < 4; j++)
#pragma unroll
                for (int e = 0; e < 4; e++) S[j][e] = 0.f;
#pragma unroll
            for (int ds = 0; ds < 2; ds++) {
#pragma unroll
                for (int jl = 0; jl < 2; jl++) {
                    const int jp = 2 * ch + jl;
                    unsigned b0a, b1a, b0b, b1b;
                    int row = 16 * ds + (lane & 7) + ((lane & 8) ? 8 : 0);
                    int col = 16 * jp + ((lane >= 16) ? 8 : 0);
                    ldsm4t(b0a, b1a, b0b, b1b, saddr(&Kds[row * QP + col]));
                    mma16(S[2 * jl],     aQ[ds], b0a, b1a);
                    mma16(S[2 * jl + 1], aQ[ds], b0b, b1b);
                }
            }
            // l-row B fragments (shared across clusters)
            unsigned ul[2][2];
#pragma unroll
            for (int kl = 0; kl < 2; kl++) {
                int kk = 2 * ch + kl;
                ldsm2(ul[kl][0], ul[kl][1],
                      saddr(&Vh[(32 + (lane & 7)) * QP + 16 * kk + ((lane & 8) ? 8 : 0)]));
            }
            // 3 clusters: folded-exponent softmax + PV + l
#pragma unroll
            for (int i = 0; i < KC; i++) {
                const float q0c = qc[i][0], q1c = qc[i][1];
                unsigned aP[2][4];
#pragma unroll
                for (int j = 0; j < 4; j++) {
                    const float4 pv = *(const float4*)&probKs[(i * 64 + ch * 32 + 8 * j + 2 * tg) * 2];
                    float a00 = fmaf(q0c * pv.x, S[j][0], pv.y);
                    float a01 = fmaf(q0c * pv.z, S[j][1], pv.w);
                    float a10 = fmaf(q1c * pv.x, S[j][2], pv.y);
                    float a11 = fmaf(q1c * pv.z, S[j][3], pv.w);
                    aP[j >> 1][(j & 1) * 2]     = ex2h2(pack_h2(a00, a01));
                    aP[j >> 1][(j & 1) * 2 + 1] = ex2h2(pack_h2(a10, a11));
                }
#pragma unroll
                for (int kl = 0; kl < 2; kl++) {
                    const int kk = 2 * ch + kl;
#pragma unroll
                    for (int jp = 0; jp < 2; jp++) {
                        unsigned v0, v1, v2, v3;
                        int row = 8 * (2 * jp + ((lane >= 16) ? 1 : 0)) + (lane & 7);
                        int col = 16 * kk + ((lane & 8) ? 8 : 0);
                        ldsm4(v0, v1, v2, v3, saddr(&Vh[row * QP + col]));
                        mma16(acc[i][2 * jp],     aP[kl], v0, v1);
                        mma16(acc[i][2 * jp + 1], aP[kl], v2, v3);
                    }
                    mma16(accl[i], aP[kl], ul[kl][0], ul[kl][1]);
                }
            }
        }
        __syncthreads();
    }

    // Epilogue: l at cols 32+i (cluster i): i=0 -> tg0 c0/c2; i=1 -> tg0 c1/c3;
    // i=2 -> tg1 c0/c2. Broadcast within quad.
    const int src = lane & ~3;
    float l0g  = __shfl_sync(0xffffffffu, accl[0][0], src);
    float l0g8 = __shfl_sync(0xffffffffu, accl[0][2], src);
    float l1g  = __shfl_sync(0xffffffffu, accl[1][1], src);
    float l1g8 = __shfl_sync(0xffffffffu, accl[1][3], src);
    float l2g  = __shfl_sync(0xffffffffu, accl[2][0], src + 1);
    float l2g8 = __shfl_sync(0xffffffffu, accl[2][2], src + 1);
    float r0[KC], r1[KC];
    r0[0] = 1.f / (3.f * l0g);  r1[0] = 1.f / (3.f * l0g8);
    r0[1] = 1.f / (3.f * l1g);  r1[1] = 1.f / (3.f * l1g8);
    r0[2] = 1.f / (3.f * l2g);  r1[2] = 1.f / (3.f * l2g8);

    float* Os = (float*)sm;  // [32][65] overlay (Q/K region)
    const int qg = 16 * w + g;
#pragma unroll
    for (int jn = 0; jn < 4; jn++) {
        int d0 = 8 * jn + 2 * tg;
        float o00 = acc[0][jn][0] * r0[0] + acc[1][jn][0] * r0[1] + acc[2][jn][0] * r0[2];
        float o01 = acc[0][jn][1] * r0[0] + acc[1][jn][1] * r0[1] + acc[2][jn][1] * r0[2];
        float o10 = acc[0][jn][2] * r1[0] + acc[1][jn][2] * r1[1] + acc[2][jn][2] * r1[2];
        float o11 = acc[0][jn][3] * r1[0] + acc[1][jn][3] * r1[1] + acc[2][jn][3] * r1[2];
        Os[d0 * 65 + qg]           = o00;
        Os[(d0 + 1) * 65 + qg]     = o01;
        Os[d0 * 65 + qg + 8]       = o10;
        Os[(d0 + 1) * 65 + qg + 8] = o11;
    }
    __syncthreads();
    float* ob = g_att + (size_t)(b * C2 + h * DD) * NN;
#pragma unroll
    for (int j = 0; j < 16; j++) {
        int i = t + 128 * j, d = i >> 6, q = i & 63;
        ob[(size_t)d * NN + q0 + q] = Os[d * 65 + q];
    }
}

// ---------------------------------------------------------------------------
extern "C" void kernel_launch(void* const* d_in, const int* in_sizes, int n_in,
                              void* d_out, int out_size)
{
    const float* x         = (const float*)d_in[0];
    const float* W_in      = (const float*)d_in[1];
    const float* W_cluster = (const float*)d_in[2];
    const float* b_cluster = (const float*)d_in[3];
    const float* W_qkv     = (const float*)d_in[4];
    const float* W_proj    = (const float*)d_in[5];
    float* out = (float*)d_out;

    float *xf, *att;
    __half* qkvh;
    cudaGetSymbolAddress((void**)&xf,   g_xf);
    cudaGetSymbolAddress((void**)&att,  g_att);
    cudaGetSymbolAddress((void**)&qkvh, g_qkvh);

    // proj_in (fp32 SIMT — residual identity path)
    gemm128<<<dim3(NN / 128, C2 / 128, BB), 256>>>(W_in, x, xf, C2, NN, C1);
    // cluster probs (pk, log2 pk)
    cluster_kernel<<<dim3(NN / 128, BB), 256>>>(W_cluster, b_cluster);
    // qkv (f16 tensor, f16 output)
    gemm_f16<2><<<dim3(NN / 128, 768 / 128, BB), 256>>>(W_qkv, xf, (float*)qkvh, nullptr, 3 * C2, NN, C2);
    // clustered attention
    attn_kernel<<<dim3(NN / 64, HEADS, BB), 128>>>();
    // proj_out + residual (f16 tensor, fp32 residual add)
    gemm_f16<1><<<dim3(NN / 128, C2 / 128, BB), 256>>>(W_proj, att, out, xf, C2, NN, C2);
}